// round 4
// baseline (speedup 1.0000x reference)
#include <cuda_runtime.h>
#include <math.h>

// Problem constants (SVDHead: B=1024, N=8192, 3D points)
#define BATCH 1024
#define NPTS  8192
#define NTHREADS 256
#define CHUNKS_PER_THREAD (NPTS / 4 / NTHREADS)   // 8 (4 points per float4-chunk)

// ---------------------------------------------------------------------------
// Fused kernel: one CTA per batch.
//   Phase 1: 256-thread float4 streaming reduction of 16 sums.
//   Phase 2: thread 0 does the fp32 3x3 Kabsch solve in-register and writes R,t.
// All 1024 CTAs fit in one wave (256 thr, <=32 regs, 8 CTAs/SM), so the
// per-CTA solve tails overlap chip-wide.
// ---------------------------------------------------------------------------
__device__ __forceinline__ void acc_point(float acc[16],
                                          float wn,
                                          float s0, float s1, float s2,
                                          float t0, float t1, float t2)
{
    acc[0] += wn;
    const float ws0 = wn * s0, ws1 = wn * s1, ws2 = wn * s2;
    acc[1] += ws0;  acc[2] += ws1;  acc[3] += ws2;
    acc[4] += wn*t0; acc[5] += wn*t1; acc[6] += wn*t2;
    acc[7]  += ws0*t0; acc[8]  += ws0*t1; acc[9]  += ws0*t2;
    acc[10] += ws1*t0; acc[11] += ws1*t1; acc[12] += ws1*t2;
    acc[13] += ws2*t0; acc[14] += ws2*t1; acc[15] += ws2*t2;
}

__global__ __launch_bounds__(NTHREADS, 8)
void svd_head_fused_kernel(const float* __restrict__ src,
                           const float* __restrict__ tpl,
                           const float* __restrict__ wts,
                           float* __restrict__ out)
{
    const int b   = blockIdx.x;
    const int tid = threadIdx.x;

    const float4* __restrict__ sv = (const float4*)(src + (size_t)b * NPTS * 3);
    const float4* __restrict__ tv = (const float4*)(tpl + (size_t)b * NPTS * 3);
    const float4* __restrict__ wv = (const float4*)(wts + (size_t)b * NPTS);

    float acc[16];
#pragma unroll
    for (int i = 0; i < 16; i++) acc[i] = 0.0f;

#pragma unroll 4
    for (int k = 0; k < CHUNKS_PER_THREAD; k++) {
        const int i = tid + k * NTHREADS;           // chunk of 4 points
        const float4 w4 = wv[i];
        const float4 sa = sv[3*i+0];
        const float4 sb = sv[3*i+1];
        const float4 sc4 = sv[3*i+2];
        const float4 ta = tv[3*i+0];
        const float4 tb = tv[3*i+1];
        const float4 tc4 = tv[3*i+2];

        acc_point(acc, w4.x, sa.x, sa.y, sa.z, ta.x, ta.y, ta.z);
        acc_point(acc, w4.y, sa.w, sb.x, sb.y, ta.w, tb.x, tb.y);
        acc_point(acc, w4.z, sb.z, sb.w, sc4.x, tb.z, tb.w, tc4.x);
        acc_point(acc, w4.w, sc4.y, sc4.z, sc4.w, tc4.y, tc4.z, tc4.w);
    }

    // Warp reduce all 16, then cross-warp via smem.
    __shared__ float red[(NTHREADS/32) * 16];
    __shared__ float fin[16];
    const int lane = tid & 31;
    const int wrp  = tid >> 5;

#pragma unroll
    for (int i = 0; i < 16; i++) {
        float v = acc[i];
#pragma unroll
        for (int off = 16; off > 0; off >>= 1)
            v += __shfl_down_sync(0xffffffffu, v, off);
        if (lane == 0) red[wrp * 16 + i] = v;
    }
    __syncthreads();

    if (tid < 16) {
        float v = 0.0f;
#pragma unroll
        for (int k = 0; k < NTHREADS/32; k++) v += red[k * 16 + tid];
        fin[tid] = v;
    }
    __syncthreads();

    if (tid != 0) return;

    // ------------------ fp32 3x3 Kabsch solve (thread 0) ------------------
    const float Wsum  = fin[0];
    const float inv_d = __fdividef(1.0f, Wsum + 1e-8f);
    const float S     = Wsum * inv_d;   // sum of normalized weights (~1)

    float sc[3], tc[3];
#pragma unroll
    for (int i = 0; i < 3; i++) {
        sc[i] = fin[1 + i] * inv_d;
        tc[i] = fin[4 + i] * inv_d;
    }

    // H = M/denom + (S-2)*sc tc^T  where M = sum wn s t^T
    float H[3][3];
#pragma unroll
    for (int i = 0; i < 3; i++)
#pragma unroll
        for (int j = 0; j < 3; j++)
            H[i][j] = fin[7 + 3*i + j] * inv_d + (S - 2.0f) * sc[i] * tc[j];

    // A = H^T H  (symmetric PSD)
    float A[3][3];
#pragma unroll
    for (int i = 0; i < 3; i++)
#pragma unroll
        for (int j = 0; j < 3; j++) {
            float a2 = 0.0f;
#pragma unroll
            for (int k = 0; k < 3; k++) a2 += H[k][i] * H[k][j];
            A[i][j] = a2;
        }

    // Scale for numerical headroom in fp32.
    float amax = 1e-30f;
#pragma unroll
    for (int i = 0; i < 3; i++)
#pragma unroll
        for (int j = 0; j < 3; j++) amax = fmaxf(amax, fabsf(A[i][j]));
    const float ainv = __fdividef(1.0f, amax);
#pragma unroll
    for (int i = 0; i < 3; i++)
#pragma unroll
        for (int j = 0; j < 3; j++) A[i][j] *= ainv;

    // Cyclic Jacobi eigen-decomposition: A = V diag(d) V^T
    float V[3][3] = {{1,0,0},{0,1,0},{0,0,1}};
#pragma unroll 1
    for (int sweep = 0; sweep < 8; sweep++) {
        const float off = A[0][1]*A[0][1] + A[0][2]*A[0][2] + A[1][2]*A[1][2];
        if (off < 1e-20f) break;
#pragma unroll
        for (int pair = 0; pair < 3; pair++) {
            const int p = (pair == 2) ? 1 : 0;
            const int q = (pair == 0) ? 1 : 2;
            const float apq = A[p][q];
            if (fabsf(apq) < 1e-30f) continue;
            const float tau = __fdividef(A[q][q] - A[p][p], 2.0f * apq);
            const float tt  = __fdividef(copysignf(1.0f, tau),
                                         fabsf(tau) + sqrtf(1.0f + tau*tau));
            const float c   = rsqrtf(1.0f + tt*tt);
            const float sn  = tt * c;
#pragma unroll
            for (int k = 0; k < 3; k++) {
                const float apk = A[p][k], aqk = A[q][k];
                A[p][k] = c*apk - sn*aqk;
                A[q][k] = sn*apk + c*aqk;
            }
#pragma unroll
            for (int k = 0; k < 3; k++) {
                const float akp = A[k][p], akq = A[k][q];
                A[k][p] = c*akp - sn*akq;
                A[k][q] = sn*akp + c*akq;
                const float vkp = V[k][p], vkq = V[k][q];
                V[k][p] = c*vkp - sn*vkq;
                V[k][q] = sn*vkp + c*vkq;
            }
        }
    }

    // Sort eigenvalues descending.
    int idx[3] = {0, 1, 2};
    float dv[3] = {A[0][0], A[1][1], A[2][2]};
    if (dv[idx[0]] < dv[idx[1]]) { int t_ = idx[0]; idx[0] = idx[1]; idx[1] = t_; }
    if (dv[idx[0]] < dv[idx[2]]) { int t_ = idx[0]; idx[0] = idx[2]; idx[2] = t_; }
    if (dv[idx[1]] < dv[idx[2]]) { int t_ = idx[1]; idx[1] = idx[2]; idx[2] = t_; }

    float Vs[3][3];   // Vs[:][i] = i-th right singular vector (desc sigma)
#pragma unroll
    for (int i = 0; i < 3; i++)
#pragma unroll
        for (int r = 0; r < 3; r++) Vs[r][i] = V[r][idx[i]];

    // U columns: u_i = normalize(H v_i), Gram-Schmidt.
    float U[3][3];
#pragma unroll
    for (int i = 0; i < 3; i++) {
        float u[3];
#pragma unroll
        for (int r = 0; r < 3; r++)
            u[r] = H[r][0]*Vs[0][i] + H[r][1]*Vs[1][i] + H[r][2]*Vs[2][i];
#pragma unroll
        for (int j = 0; j < 3; j++) {
            if (j >= i) break;
            const float dp = u[0]*U[0][j] + u[1]*U[1][j] + u[2]*U[2][j];
            u[0] -= dp*U[0][j]; u[1] -= dp*U[1][j]; u[2] -= dp*U[2][j];
        }
        const float n2 = u[0]*u[0] + u[1]*u[1] + u[2]*u[2];
        if (n2 > 1e-24f) {
            const float inv = rsqrtf(n2);
            U[0][i] = u[0]*inv; U[1][i] = u[1]*inv; U[2][i] = u[2]*inv;
        } else {
            if (i == 2) {
                U[0][2] = U[1][0]*U[2][1] - U[2][0]*U[1][1];
                U[1][2] = U[2][0]*U[0][1] - U[0][0]*U[2][1];
                U[2][2] = U[0][0]*U[1][1] - U[1][0]*U[0][1];
            } else if (i == 1) {
                float a0 = 1, a1 = 0;
                if (fabsf(U[0][0]) > 0.9f) { a0 = 0; a1 = 1; }
                float u1[3] = {
                    a1*U[2][0],
                    -a0*U[2][0],
                    a0*U[1][0] - a1*U[0][0]
                };
                const float n1 = rsqrtf(u1[0]*u1[0]+u1[1]*u1[1]+u1[2]*u1[2] + 1e-30f);
                U[0][1] = u1[0]*n1; U[1][1] = u1[1]*n1; U[2][1] = u1[2]*n1;
            } else {
                U[0][0] = 1; U[1][0] = 0; U[2][0] = 0;
            }
        }
    }

    // R_pos = Vs * U^T
    float R[3][3];
#pragma unroll
    for (int i = 0; i < 3; i++)
#pragma unroll
        for (int j = 0; j < 3; j++)
            R[i][j] = Vs[i][0]*U[j][0] + Vs[i][1]*U[j][1] + Vs[i][2]*U[j][2];

    const float det =
          R[0][0]*(R[1][1]*R[2][2] - R[1][2]*R[2][1])
        - R[0][1]*(R[1][0]*R[2][2] - R[1][2]*R[2][0])
        + R[0][2]*(R[1][0]*R[2][1] - R[1][1]*R[2][0]);

    if (!(det > 0.0f)) {
#pragma unroll
        for (int i = 0; i < 3; i++)
#pragma unroll
            for (int j = 0; j < 3; j++)
                R[i][j] -= 2.0f * Vs[i][2] * U[j][2];
    }

    float tvv[3];
#pragma unroll
    for (int i = 0; i < 3; i++)
        tvv[i] = -(R[i][0]*sc[0] + R[i][1]*sc[1] + R[i][2]*sc[2]) + tc[i];

    float* __restrict__ Rout = out + (size_t)b * 9;
    float* __restrict__ Tout = out + (size_t)BATCH * 9 + (size_t)b * 3;
#pragma unroll
    for (int i = 0; i < 3; i++) {
#pragma unroll
        for (int j = 0; j < 3; j++) Rout[3*i + j] = R[i][j];
        Tout[i] = tvv[i];
    }
}

extern "C" void kernel_launch(void* const* d_in, const int* in_sizes, int n_in,
                              void* d_out, int out_size)
{
    const float* src = (const float*)d_in[0];  // [B, N, 3]
    const float* tpl = (const float*)d_in[1];  // [B, N, 3]
    const float* wts = (const float*)d_in[2];  // [B, N]
    float* out = (float*)d_out;                // [B*9 + B*3]

    svd_head_fused_kernel<<<BATCH, NTHREADS>>>(src, tpl, wts, out);
}

// round 5
// speedup vs baseline: 2.2351x; 2.2351x over previous
#include <cuda_runtime.h>
#include <math.h>

// Problem constants (SVDHead: B=1024, N=8192, 3D points)
#define BATCH 1024
#define NPTS  8192
#define NTHREADS 256
#define CHUNKS_PER_THREAD (NPTS / 4 / NTHREADS)   // 8 (4 points per float4-chunk)

// Per-batch reduced sums: [0]=sum w, [1..3]=sum w*s, [4..6]=sum w*t,
// [7..15]=sum w*s_i*t_j (row-major i,j)
__device__ float g_sums[BATCH * 16];

// ---------------------------------------------------------------------------
// Kernel 1: pure memory-bound reduction. One CTA per batch, float4 loads.
// (identical to the 46.8us round-3 version)
// ---------------------------------------------------------------------------
__device__ __forceinline__ void acc_point(float acc[16],
                                          float wn,
                                          float s0, float s1, float s2,
                                          float t0, float t1, float t2)
{
    acc[0] += wn;
    const float ws0 = wn * s0, ws1 = wn * s1, ws2 = wn * s2;
    acc[1] += ws0;  acc[2] += ws1;  acc[3] += ws2;
    acc[4] += wn*t0; acc[5] += wn*t1; acc[6] += wn*t2;
    acc[7]  += ws0*t0; acc[8]  += ws0*t1; acc[9]  += ws0*t2;
    acc[10] += ws1*t0; acc[11] += ws1*t1; acc[12] += ws1*t2;
    acc[13] += ws2*t0; acc[14] += ws2*t1; acc[15] += ws2*t2;
}

__global__ __launch_bounds__(NTHREADS)
void svd_reduce_kernel(const float* __restrict__ src,
                       const float* __restrict__ tpl,
                       const float* __restrict__ wts)
{
    const int b   = blockIdx.x;
    const int tid = threadIdx.x;

    const float4* __restrict__ sv = (const float4*)(src + (size_t)b * NPTS * 3);
    const float4* __restrict__ tv = (const float4*)(tpl + (size_t)b * NPTS * 3);
    const float4* __restrict__ wv = (const float4*)(wts + (size_t)b * NPTS);

    float acc[16];
#pragma unroll
    for (int i = 0; i < 16; i++) acc[i] = 0.0f;

#pragma unroll 4
    for (int k = 0; k < CHUNKS_PER_THREAD; k++) {
        const int i = tid + k * NTHREADS;           // chunk of 4 points
        const float4 w4 = wv[i];
        const float4 sa = sv[3*i+0];
        const float4 sb = sv[3*i+1];
        const float4 sc = sv[3*i+2];
        const float4 ta = tv[3*i+0];
        const float4 tb = tv[3*i+1];
        const float4 tc = tv[3*i+2];

        acc_point(acc, w4.x, sa.x, sa.y, sa.z, ta.x, ta.y, ta.z);
        acc_point(acc, w4.y, sa.w, sb.x, sb.y, ta.w, tb.x, tb.y);
        acc_point(acc, w4.z, sb.z, sb.w, sc.x, tb.z, tb.w, tc.x);
        acc_point(acc, w4.w, sc.y, sc.z, sc.w, tc.y, tc.z, tc.w);
    }

    // Warp reduce all 16, then cross-warp via smem.
    __shared__ float red[(NTHREADS/32) * 16];
    const int lane = tid & 31;
    const int wrp  = tid >> 5;

#pragma unroll
    for (int i = 0; i < 16; i++) {
        float v = acc[i];
#pragma unroll
        for (int off = 16; off > 0; off >>= 1)
            v += __shfl_down_sync(0xffffffffu, v, off);
        if (lane == 0) red[wrp * 16 + i] = v;
    }
    __syncthreads();

    if (tid < 16) {
        float v = 0.0f;
#pragma unroll
        for (int k = 0; k < NTHREADS/32; k++) v += red[k * 16 + tid];
        g_sums[b * 16 + tid] = v;
    }
}

// ---------------------------------------------------------------------------
// Kernel 2: per-batch 3x3 solve, fp32. ONE BLOCK PER BATCH, lane 0 solves.
// grid=1024 spreads blocks across all SMs (vs. the grid=4 packing that
// serialized round 3); fp32 + fast-math intrinsics shorten the latency chain
// ~4x vs the fp64 round-2 version.
// ---------------------------------------------------------------------------
__global__ __launch_bounds__(32)
void svd_solve_kernel(float* __restrict__ out)
{
    const int b = blockIdx.x;
    if (threadIdx.x != 0) return;

    float fin[16];
#pragma unroll
    for (int i = 0; i < 16; i++) fin[i] = g_sums[b * 16 + i];

    const float Wsum  = fin[0];
    const float inv_d = __fdividef(1.0f, Wsum + 1e-8f);
    const float S     = Wsum * inv_d;   // sum of normalized weights (~1)

    float sc[3], tc[3];
#pragma unroll
    for (int i = 0; i < 3; i++) {
        sc[i] = fin[1 + i] * inv_d;
        tc[i] = fin[4 + i] * inv_d;
    }

    // H = M/denom + (S-2)*sc tc^T  where M = sum wn s t^T
    float H[3][3];
#pragma unroll
    for (int i = 0; i < 3; i++)
#pragma unroll
        for (int j = 0; j < 3; j++)
            H[i][j] = fin[7 + 3*i + j] * inv_d + (S - 2.0f) * sc[i] * tc[j];

    // A = H^T H  (symmetric PSD)
    float A[3][3];
#pragma unroll
    for (int i = 0; i < 3; i++)
#pragma unroll
        for (int j = 0; j < 3; j++) {
            float a2 = 0.0f;
#pragma unroll
            for (int k = 0; k < 3; k++) a2 += H[k][i] * H[k][j];
            A[i][j] = a2;
        }

    // Scale for numerical headroom in fp32.
    float amax = 1e-30f;
#pragma unroll
    for (int i = 0; i < 3; i++)
#pragma unroll
        for (int j = 0; j < 3; j++) amax = fmaxf(amax, fabsf(A[i][j]));
    const float ainv = __fdividef(1.0f, amax);
#pragma unroll
    for (int i = 0; i < 3; i++)
#pragma unroll
        for (int j = 0; j < 3; j++) A[i][j] *= ainv;

    // Cyclic Jacobi eigen-decomposition: A = V diag(d) V^T
    float V[3][3] = {{1,0,0},{0,1,0},{0,0,1}};
#pragma unroll 1
    for (int sweep = 0; sweep < 8; sweep++) {
        const float off = A[0][1]*A[0][1] + A[0][2]*A[0][2] + A[1][2]*A[1][2];
        if (off < 1e-20f) break;
#pragma unroll
        for (int pair = 0; pair < 3; pair++) {
            const int p = (pair == 2) ? 1 : 0;
            const int q = (pair == 0) ? 1 : 2;
            const float apq = A[p][q];
            if (fabsf(apq) < 1e-30f) continue;
            const float tau = __fdividef(A[q][q] - A[p][p], 2.0f * apq);
            const float tt  = __fdividef(copysignf(1.0f, tau),
                                         fabsf(tau) + sqrtf(1.0f + tau*tau));
            const float c   = rsqrtf(1.0f + tt*tt);
            const float sn  = tt * c;
#pragma unroll
            for (int k = 0; k < 3; k++) {
                const float apk = A[p][k], aqk = A[q][k];
                A[p][k] = c*apk - sn*aqk;
                A[q][k] = sn*apk + c*aqk;
            }
#pragma unroll
            for (int k = 0; k < 3; k++) {
                const float akp = A[k][p], akq = A[k][q];
                A[k][p] = c*akp - sn*akq;
                A[k][q] = sn*akp + c*akq;
                const float vkp = V[k][p], vkq = V[k][q];
                V[k][p] = c*vkp - sn*vkq;
                V[k][q] = sn*vkp + c*vkq;
            }
        }
    }

    // Sort eigenvalues descending.
    int idx[3] = {0, 1, 2};
    float dv[3] = {A[0][0], A[1][1], A[2][2]};
    if (dv[idx[0]] < dv[idx[1]]) { int t_ = idx[0]; idx[0] = idx[1]; idx[1] = t_; }
    if (dv[idx[0]] < dv[idx[2]]) { int t_ = idx[0]; idx[0] = idx[2]; idx[2] = t_; }
    if (dv[idx[1]] < dv[idx[2]]) { int t_ = idx[1]; idx[1] = idx[2]; idx[2] = t_; }

    float Vs[3][3];   // Vs[:][i] = i-th right singular vector (desc sigma)
#pragma unroll
    for (int i = 0; i < 3; i++)
#pragma unroll
        for (int r = 0; r < 3; r++) Vs[r][i] = V[r][idx[i]];

    // U columns: u_i = normalize(H v_i), Gram-Schmidt.
    float U[3][3];
#pragma unroll
    for (int i = 0; i < 3; i++) {
        float u[3];
#pragma unroll
        for (int r = 0; r < 3; r++)
            u[r] = H[r][0]*Vs[0][i] + H[r][1]*Vs[1][i] + H[r][2]*Vs[2][i];
#pragma unroll
        for (int j = 0; j < 3; j++) {
            if (j >= i) break;
            const float dp = u[0]*U[0][j] + u[1]*U[1][j] + u[2]*U[2][j];
            u[0] -= dp*U[0][j]; u[1] -= dp*U[1][j]; u[2] -= dp*U[2][j];
        }
        const float n2 = u[0]*u[0] + u[1]*u[1] + u[2]*u[2];
        if (n2 > 1e-24f) {
            const float inv = rsqrtf(n2);
            U[0][i] = u[0]*inv; U[1][i] = u[1]*inv; U[2][i] = u[2]*inv;
        } else {
            if (i == 2) {
                U[0][2] = U[1][0]*U[2][1] - U[2][0]*U[1][1];
                U[1][2] = U[2][0]*U[0][1] - U[0][0]*U[2][1];
                U[2][2] = U[0][0]*U[1][1] - U[1][0]*U[0][1];
            } else if (i == 1) {
                float a0 = 1, a1 = 0;
                if (fabsf(U[0][0]) > 0.9f) { a0 = 0; a1 = 1; }
                float u1[3] = {
                    a1*U[2][0],
                    -a0*U[2][0],
                    a0*U[1][0] - a1*U[0][0]
                };
                const float n1 = rsqrtf(u1[0]*u1[0]+u1[1]*u1[1]+u1[2]*u1[2] + 1e-30f);
                U[0][1] = u1[0]*n1; U[1][1] = u1[1]*n1; U[2][1] = u1[2]*n1;
            } else {
                U[0][0] = 1; U[1][0] = 0; U[2][0] = 0;
            }
        }
    }

    // R_pos = Vs * U^T
    float R[3][3];
#pragma unroll
    for (int i = 0; i < 3; i++)
#pragma unroll
        for (int j = 0; j < 3; j++)
            R[i][j] = Vs[i][0]*U[j][0] + Vs[i][1]*U[j][1] + Vs[i][2]*U[j][2];

    const float det =
          R[0][0]*(R[1][1]*R[2][2] - R[1][2]*R[2][1])
        - R[0][1]*(R[1][0]*R[2][2] - R[1][2]*R[2][0])
        + R[0][2]*(R[1][0]*R[2][1] - R[1][1]*R[2][0]);

    if (!(det > 0.0f)) {
#pragma unroll
        for (int i = 0; i < 3; i++)
#pragma unroll
            for (int j = 0; j < 3; j++)
                R[i][j] -= 2.0f * Vs[i][2] * U[j][2];
    }

    float tvv[3];
#pragma unroll
    for (int i = 0; i < 3; i++)
        tvv[i] = -(R[i][0]*sc[0] + R[i][1]*sc[1] + R[i][2]*sc[2]) + tc[i];

    float* __restrict__ Rout = out + (size_t)b * 9;
    float* __restrict__ Tout = out + (size_t)BATCH * 9 + (size_t)b * 3;
#pragma unroll
    for (int i = 0; i < 3; i++) {
#pragma unroll
        for (int j = 0; j < 3; j++) Rout[3*i + j] = R[i][j];
        Tout[i] = tvv[i];
    }
}

extern "C" void kernel_launch(void* const* d_in, const int* in_sizes, int n_in,
                              void* d_out, int out_size)
{
    const float* src = (const float*)d_in[0];  // [B, N, 3]
    const float* tpl = (const float*)d_in[1];  // [B, N, 3]
    const float* wts = (const float*)d_in[2];  // [B, N]
    float* out = (float*)d_out;                // [B*9 + B*3]

    svd_reduce_kernel<<<BATCH, NTHREADS>>>(src, tpl, wts);
    svd_solve_kernel<<<BATCH, 32>>>(out);
}